// round 3
// baseline (speedup 1.0000x reference)
#include <cuda_runtime.h>
#include <cuda_bf16.h>

// Per-node precomputed scores. __device__ globals are the sanctioned scratch.
#define MAX_NODES 65536
__device__ float g_uscore[MAX_NODES];
__device__ float g_iscore[MAX_NODES];

// ---------------------------------------------------------------------------
// Kernel 1: per-node dot products. One warp per node row.
// Rows [0, Nu)     : g_uscore[r]    = dot(user_feats[r], W[0:128])
// Rows [Nu, Nu+Ni) : g_iscore[r-Nu] = dot(item_feats[r-Nu], W[128:256])
// 128 floats per row = 32 lanes x float4, then warp shuffle reduction.
// ---------------------------------------------------------------------------
__global__ void node_score_kernel(const float* __restrict__ user_feats,
                                  const float* __restrict__ item_feats,
                                  const float* __restrict__ W,
                                  int Nu, int Ni)
{
    const int warps_per_block = blockDim.x >> 5;
    const int row  = blockIdx.x * warps_per_block + (threadIdx.x >> 5);
    const int lane = threadIdx.x & 31;
    if (row >= Nu + Ni) return;

    const float4* feat;
    const float4* w;
    if (row < Nu) {
        feat = reinterpret_cast<const float4*>(user_feats) + (size_t)row * 32;
        w    = reinterpret_cast<const float4*>(W);          // W[0:128]
    } else {
        feat = reinterpret_cast<const float4*>(item_feats) + (size_t)(row - Nu) * 32;
        w    = reinterpret_cast<const float4*>(W) + 32;     // W[128:256]
    }

    const float4 v  = feat[lane];
    const float4 ww = w[lane];
    float s = v.x * ww.x + v.y * ww.y + v.z * ww.z + v.w * ww.w;

    #pragma unroll
    for (int o = 16; o > 0; o >>= 1)
        s += __shfl_xor_sync(0xffffffffu, s, o);

    if (lane == 0) {
        if (row < Nu) g_uscore[row]      = s;
        else          g_iscore[row - Nu] = s;
    }
}

// ---------------------------------------------------------------------------
// Kernel 2: per-edge score = u_score[src] + i_score[dst] + b[0].
// Indices are INT32 (JAX demotes int64 without x64 mode).
// Score tables (2 x 200 KB) are L2-resident after kernel 1.
// ---------------------------------------------------------------------------
__global__ void edge_score_kernel(const int* __restrict__ src_idx,
                                  const int* __restrict__ dst_idx,
                                  const float* __restrict__ b,
                                  float* __restrict__ out,
                                  int E)
{
    const float b0 = b[0];
    int e = blockIdx.x * blockDim.x + threadIdx.x;
    const int stride = gridDim.x * blockDim.x;
    for (; e < E; e += stride) {
        const int su = src_idx[e];
        const int di = dst_idx[e];
        out[e] = g_uscore[su] + g_iscore[di] + b0;
    }
}

// ---------------------------------------------------------------------------
// Inputs (metadata order): user_feats f32 [Nu,128], item_feats f32 [Ni,128],
// src_idx i32 [E], dst_idx i32 [E], W f32 [256,1], b f32 [1].
// Output: f32 [E,1].
// ---------------------------------------------------------------------------
extern "C" void kernel_launch(void* const* d_in, const int* in_sizes, int n_in,
                              void* d_out, int out_size)
{
    const float* user_feats = (const float*)d_in[0];
    const float* item_feats = (const float*)d_in[1];
    const int*   src_idx    = (const int*)d_in[2];
    const int*   dst_idx    = (const int*)d_in[3];
    const float* W          = (const float*)d_in[4];
    const float* b          = (const float*)d_in[5];
    float*       out        = (float*)d_out;

    const int Nu = in_sizes[0] / 128;
    const int Ni = in_sizes[1] / 128;
    const int E  = in_sizes[2];

    // Kernel 1: one warp per node row; 8 warps per block.
    {
        const int total_rows = Nu + Ni;
        const int warps_per_block = 8;
        const int blocks = (total_rows + warps_per_block - 1) / warps_per_block;
        node_score_kernel<<<blocks, warps_per_block * 32>>>(
            user_feats, item_feats, W, Nu, Ni);
    }

    // Kernel 2: grid-stride over edges.
    {
        const int threads = 256;
        int blocks = (E + threads - 1) / threads;
        if (blocks > 4096) blocks = 4096;
        edge_score_kernel<<<blocks, threads>>>(src_idx, dst_idx, b, out, E);
    }
}

// round 4
// speedup vs baseline: 1.0646x; 1.0646x over previous
#include <cuda_runtime.h>
#include <cuda_bf16.h>

// Per-node precomputed scores. __device__ globals are the sanctioned scratch.
#define MAX_NODES 65536
__device__ float g_uscore[MAX_NODES];
__device__ float g_iscore[MAX_NODES];

// ---------------------------------------------------------------------------
// Kernel 1: per-node dot products. One warp per TWO node rows (ILP=2).
// Rows [0, Nu)     : g_uscore[r]    = dot(user_feats[r], W[0:128])
// Rows [Nu, Nu+Ni) : g_iscore[r-Nu] = dot(item_feats[r-Nu], W[128:256])
// ---------------------------------------------------------------------------
__device__ __forceinline__ void row_ptrs(int row, int Nu,
                                         const float* user_feats,
                                         const float* item_feats,
                                         const float4** feat,
                                         const float4** w)
{
    if (row < Nu) {
        *feat = reinterpret_cast<const float4*>(user_feats) + (size_t)row * 32;
        *w    = reinterpret_cast<const float4*>(user_feats); // placeholder, fixed below
        *w    = nullptr;
    }
}

__global__ void node_score_kernel(const float* __restrict__ user_feats,
                                  const float* __restrict__ item_feats,
                                  const float* __restrict__ W,
                                  int Nu, int Ni)
{
    const int warps_per_block = blockDim.x >> 5;
    const int warp = blockIdx.x * warps_per_block + (threadIdx.x >> 5);
    const int lane = threadIdx.x & 31;
    const int total = Nu + Ni;

    const int row0 = warp * 2;
    const int row1 = row0 + 1;
    if (row0 >= total) return;

    const float4* Wu = reinterpret_cast<const float4*>(W);       // W[0:128]
    const float4* Wi = Wu + 32;                                   // W[128:256]

    // Row 0 pointers
    const float4* f0;
    const float4* w0;
    if (row0 < Nu) {
        f0 = reinterpret_cast<const float4*>(user_feats) + (size_t)row0 * 32;
        w0 = Wu;
    } else {
        f0 = reinterpret_cast<const float4*>(item_feats) + (size_t)(row0 - Nu) * 32;
        w0 = Wi;
    }

    const bool has1 = (row1 < total);
    const float4* f1 = f0;
    const float4* w1 = w0;
    if (has1) {
        if (row1 < Nu) {
            f1 = reinterpret_cast<const float4*>(user_feats) + (size_t)row1 * 32;
            w1 = Wu;
        } else {
            f1 = reinterpret_cast<const float4*>(item_feats) + (size_t)(row1 - Nu) * 32;
            w1 = Wi;
        }
    }

    // Two independent load streams per lane.
    const float4 v0 = f0[lane];
    const float4 v1 = f1[lane];
    const float4 a0 = w0[lane];
    const float4 a1 = w1[lane];

    float s0 = v0.x * a0.x + v0.y * a0.y + v0.z * a0.z + v0.w * a0.w;
    float s1 = v1.x * a1.x + v1.y * a1.y + v1.z * a1.z + v1.w * a1.w;

    #pragma unroll
    for (int o = 16; o > 0; o >>= 1) {
        s0 += __shfl_xor_sync(0xffffffffu, s0, o);
        s1 += __shfl_xor_sync(0xffffffffu, s1, o);
    }

    if (lane == 0) {
        if (row0 < Nu) g_uscore[row0]      = s0;
        else           g_iscore[row0 - Nu] = s0;
        if (has1) {
            if (row1 < Nu) g_uscore[row1]      = s1;
            else           g_iscore[row1 - Nu] = s1;
        }
    }
}

// ---------------------------------------------------------------------------
// Kernel 2: per-edge score, vectorized 4 edges/thread.
// 8 independent L2-resident gathers per thread (MLP=8), float4 store.
// ---------------------------------------------------------------------------
__global__ void edge_score_kernel4(const int4* __restrict__ src_idx,
                                   const int4* __restrict__ dst_idx,
                                   const float* __restrict__ b,
                                   float4* __restrict__ out,
                                   int E4)
{
    const float b0 = b[0];
    int i = blockIdx.x * blockDim.x + threadIdx.x;
    const int stride = gridDim.x * blockDim.x;
    for (; i < E4; i += stride) {
        const int4 s = src_idx[i];
        const int4 d = dst_idx[i];
        float4 r;
        r.x = g_uscore[s.x] + g_iscore[d.x] + b0;
        r.y = g_uscore[s.y] + g_iscore[d.y] + b0;
        r.z = g_uscore[s.z] + g_iscore[d.z] + b0;
        r.w = g_uscore[s.w] + g_iscore[d.w] + b0;
        out[i] = r;
    }
}

// Scalar tail for E % 4 leftover edges (usually zero iterations).
__global__ void edge_score_tail(const int* __restrict__ src_idx,
                                const int* __restrict__ dst_idx,
                                const float* __restrict__ b,
                                float* __restrict__ out,
                                int start, int E)
{
    const float b0 = b[0];
    int e = start + threadIdx.x;
    if (e < E)
        out[e] = g_uscore[src_idx[e]] + g_iscore[dst_idx[e]] + b0;
}

// ---------------------------------------------------------------------------
// Inputs (metadata order): user_feats f32 [Nu,128], item_feats f32 [Ni,128],
// src_idx i32 [E], dst_idx i32 [E], W f32 [256,1], b f32 [1].
// Output: f32 [E,1].
// ---------------------------------------------------------------------------
extern "C" void kernel_launch(void* const* d_in, const int* in_sizes, int n_in,
                              void* d_out, int out_size)
{
    const float* user_feats = (const float*)d_in[0];
    const float* item_feats = (const float*)d_in[1];
    const int*   src_idx    = (const int*)d_in[2];
    const int*   dst_idx    = (const int*)d_in[3];
    const float* W          = (const float*)d_in[4];
    const float* b          = (const float*)d_in[5];
    float*       out        = (float*)d_out;

    const int Nu = in_sizes[0] / 128;
    const int Ni = in_sizes[1] / 128;
    const int E  = in_sizes[2];

    // Kernel 1: one warp per two node rows; 8 warps (16 rows) per block.
    {
        const int total_rows = Nu + Ni;
        const int rows_per_block = 16;
        const int blocks = (total_rows + rows_per_block - 1) / rows_per_block;
        node_score_kernel<<<blocks, 256>>>(user_feats, item_feats, W, Nu, Ni);
    }

    // Kernel 2: 4 edges per thread.
    {
        const int E4 = E / 4;
        if (E4 > 0) {
            const int threads = 256;
            int blocks = (E4 + threads - 1) / threads;
            edge_score_kernel4<<<blocks, threads>>>(
                (const int4*)src_idx, (const int4*)dst_idx, b, (float4*)out, E4);
        }
        const int tail = E - E4 * 4;
        if (tail > 0) {
            edge_score_tail<<<1, 32>>>(src_idx, dst_idx, b, out, E4 * 4, E);
        }
    }
}

// round 5
// speedup vs baseline: 1.1382x; 1.0691x over previous
#include <cuda_runtime.h>
#include <cuda_bf16.h>

// Per-node precomputed scores. __device__ globals are the sanctioned scratch.
#define MAX_NODES 65536
__device__ float g_uscore[MAX_NODES];
__device__ float g_iscore[MAX_NODES];

// ---------------------------------------------------------------------------
// Kernel 1: per-node dot products. One warp per TWO node rows (ILP=2).
// ---------------------------------------------------------------------------
__global__ void node_score_kernel(const float* __restrict__ user_feats,
                                  const float* __restrict__ item_feats,
                                  const float* __restrict__ W,
                                  int Nu, int Ni)
{
    const int warps_per_block = blockDim.x >> 5;
    const int warp = blockIdx.x * warps_per_block + (threadIdx.x >> 5);
    const int lane = threadIdx.x & 31;
    const int total = Nu + Ni;

    const int row0 = warp * 2;
    const int row1 = row0 + 1;
    if (row0 >= total) return;

    const float4* Wu = reinterpret_cast<const float4*>(W);   // W[0:128]
    const float4* Wi = Wu + 32;                               // W[128:256]

    const float4* f0;
    const float4* w0;
    if (row0 < Nu) {
        f0 = reinterpret_cast<const float4*>(user_feats) + (size_t)row0 * 32;
        w0 = Wu;
    } else {
        f0 = reinterpret_cast<const float4*>(item_feats) + (size_t)(row0 - Nu) * 32;
        w0 = Wi;
    }

    const bool has1 = (row1 < total);
    const float4* f1 = f0;
    const float4* w1 = w0;
    if (has1) {
        if (row1 < Nu) {
            f1 = reinterpret_cast<const float4*>(user_feats) + (size_t)row1 * 32;
            w1 = Wu;
        } else {
            f1 = reinterpret_cast<const float4*>(item_feats) + (size_t)(row1 - Nu) * 32;
            w1 = Wi;
        }
    }

    const float4 v0 = f0[lane];
    const float4 v1 = f1[lane];
    const float4 a0 = w0[lane];
    const float4 a1 = w1[lane];

    float s0 = v0.x * a0.x + v0.y * a0.y + v0.z * a0.z + v0.w * a0.w;
    float s1 = v1.x * a1.x + v1.y * a1.y + v1.z * a1.z + v1.w * a1.w;

    #pragma unroll
    for (int o = 16; o > 0; o >>= 1) {
        s0 += __shfl_xor_sync(0xffffffffu, s0, o);
        s1 += __shfl_xor_sync(0xffffffffu, s1, o);
    }

    if (lane == 0) {
        if (row0 < Nu) g_uscore[row0]      = s0;
        else           g_iscore[row0 - Nu] = s0;
        if (has1) {
            if (row1 < Nu) g_uscore[row1]      = s1;
            else           g_iscore[row1 - Nu] = s1;
        }
    }
}

// ---------------------------------------------------------------------------
// Kernel 2: per-edge score, 2 edges/thread.
// int2 index loads (coalesced), 4 independent L2 gathers, float2 store.
// 160k threads keep occupancy high while doubling per-thread MLP vs scalar.
// ---------------------------------------------------------------------------
__global__ void edge_score_kernel2(const int2* __restrict__ src_idx,
                                   const int2* __restrict__ dst_idx,
                                   const float* __restrict__ b,
                                   float2* __restrict__ out,
                                   int E2)
{
    const int i = blockIdx.x * blockDim.x + threadIdx.x;
    if (i >= E2) return;

    const int2 s = src_idx[i];
    const int2 d = dst_idx[i];

    // 4 independent gathers — all issued before any use.
    const float u0 = __ldg(&g_uscore[s.x]);
    const float u1 = __ldg(&g_uscore[s.y]);
    const float v0 = __ldg(&g_iscore[d.x]);
    const float v1 = __ldg(&g_iscore[d.y]);

    const float b0 = __ldg(b);
    float2 r;
    r.x = u0 + v0 + b0;
    r.y = u1 + v1 + b0;
    out[i] = r;
}

// Scalar tail for E % 2 leftover edges.
__global__ void edge_score_tail(const int* __restrict__ src_idx,
                                const int* __restrict__ dst_idx,
                                const float* __restrict__ b,
                                float* __restrict__ out,
                                int start, int E)
{
    int e = start + threadIdx.x;
    if (e < E)
        out[e] = g_uscore[src_idx[e]] + g_iscore[dst_idx[e]] + b[0];
}

// ---------------------------------------------------------------------------
// Inputs (metadata order): user_feats f32 [Nu,128], item_feats f32 [Ni,128],
// src_idx i32 [E], dst_idx i32 [E], W f32 [256,1], b f32 [1].
// Output: f32 [E,1].
// ---------------------------------------------------------------------------
extern "C" void kernel_launch(void* const* d_in, const int* in_sizes, int n_in,
                              void* d_out, int out_size)
{
    const float* user_feats = (const float*)d_in[0];
    const float* item_feats = (const float*)d_in[1];
    const int*   src_idx    = (const int*)d_in[2];
    const int*   dst_idx    = (const int*)d_in[3];
    const float* W          = (const float*)d_in[4];
    const float* b          = (const float*)d_in[5];
    float*       out        = (float*)d_out;

    const int Nu = in_sizes[0] / 128;
    const int Ni = in_sizes[1] / 128;
    const int E  = in_sizes[2];

    // Kernel 1: one warp per two node rows; 8 warps (16 rows) per block.
    {
        const int total_rows = Nu + Ni;
        const int rows_per_block = 16;
        const int blocks = (total_rows + rows_per_block - 1) / rows_per_block;
        node_score_kernel<<<blocks, 256>>>(user_feats, item_feats, W, Nu, Ni);
    }

    // Kernel 2: 2 edges per thread.
    {
        const int E2 = E / 2;
        if (E2 > 0) {
            const int threads = 256;
            const int blocks = (E2 + threads - 1) / threads;
            edge_score_kernel2<<<blocks, threads>>>(
                (const int2*)src_idx, (const int2*)dst_idx, b, (float2*)out, E2);
        }
        if (E - E2 * 2 > 0) {
            edge_score_tail<<<1, 32>>>(src_idx, dst_idx, b, out, E2 * 2, E);
        }
    }
}